// round 2
// baseline (speedup 1.0000x reference)
#include <cuda_runtime.h>
#include <cuda_bf16.h>

#define HID 256
#define TPB 128

typedef unsigned long long u64;

// ---- f32x2 packed helpers (sm_103a) ----
__device__ __forceinline__ u64 pk2(float a, float b) {
    u64 r; asm("mov.b64 %0, {%1, %2};" : "=l"(r) : "f"(a), "f"(b)); return r;
}
__device__ __forceinline__ void upk2(u64 v, float& lo, float& hi) {
    asm("mov.b64 {%0, %1}, %2;" : "=f"(lo), "=f"(hi) : "l"(v));
}
__device__ __forceinline__ u64 fma2(u64 a, u64 b, u64 c) {
    u64 d; asm("fma.rn.f32x2 %0, %1, %2, %3;" : "=l"(d) : "l"(a), "l"(b), "l"(c)); return d;
}
__device__ __forceinline__ u64 add2(u64 a, u64 b) {
    u64 d; asm("add.rn.f32x2 %0, %1, %2;" : "=l"(d) : "l"(a), "l"(b)); return d;
}
__device__ __forceinline__ u64 tanh2(u64 v) {
    float lo, hi;
    upk2(v, lo, hi);
    float tl, th;
    asm("tanh.approx.f32 %0, %1;" : "=f"(tl) : "f"(lo));
    asm("tanh.approx.f32 %0, %1;" : "=f"(th) : "f"(hi));
    return pk2(tl, th);
}

// SMEM layout: duplicated weight pairs so one LDS.128 feeds two packed operands.
//   sA[j] = { {w1x,w1x}, {w1y,w1y} }
//   sB[j] = { {b1,b1},   {hW2a,hW2a} }
//   sC[j] = { hW2b, hW2b }
__device__ __forceinline__ void geval2(u64 y0p, u64 y1p,
                                       const ulonglong2* __restrict__ sA,
                                       const ulonglong2* __restrict__ sB,
                                       const u64* __restrict__ sC,
                                       u64 hb20p, u64 hb21p,
                                       u64& o0, u64& o1)
{
    u64 a0 = 0ull, a1 = 0ull, a2 = 0ull, a3 = 0ull;
#pragma unroll 8
    for (int j = 0; j < HID; j += 2) {
        ulonglong2 A = sA[j];
        ulonglong2 B = sB[j];
        u64 pre = fma2(A.x, y0p, fma2(A.y, y1p, B.x));
        u64 t   = tanh2(pre);
        a0 = fma2(t, B.y, a0);
        a1 = fma2(t, sC[j], a1);

        ulonglong2 A1 = sA[j + 1];
        ulonglong2 B1 = sB[j + 1];
        u64 pre1 = fma2(A1.x, y0p, fma2(A1.y, y1p, B1.x));
        u64 t1   = tanh2(pre1);
        a2 = fma2(t1, B1.y, a2);
        a3 = fma2(t1, sC[j + 1], a3);
    }
    o0 = add2(add2(a0, a2), hb20p);
    o1 = add2(add2(a1, a3), hb21p);
}

__global__ __launch_bounds__(TPB)
void node_rk4_kernel(const float* __restrict__ x,
                     const float* __restrict__ W1,
                     const float* __restrict__ b1,
                     const float* __restrict__ W2,
                     const float* __restrict__ b2,
                     const float* __restrict__ Wf,
                     const float* __restrict__ bf,
                     const int*   __restrict__ tptr,
                     float* __restrict__ out,
                     int B)
{
    __shared__ ulonglong2 sA[HID];
    __shared__ ulonglong2 sB[HID];
    __shared__ u64        sC[HID];
    __shared__ float      sc[10];   // hb20, hb21, Wf00..Wf11, bf0, bf1
    __shared__ int        s_nsteps;

    const float h = 0.01f;
    const int tid = threadIdx.x;

    for (int j = tid; j < HID; j += TPB) {
        float wx = W1[j], wy = W1[HID + j], bb = b1[j];
        float wa = h * W2[2 * j], wb = h * W2[2 * j + 1];
        sA[j] = make_ulonglong2(pk2(wx, wx), pk2(wy, wy));
        sB[j] = make_ulonglong2(pk2(bb, bb), pk2(wa, wa));
        sC[j] = pk2(wb, wb);
    }
    if (tid == 0) {
        sc[0] = h * b2[0]; sc[1] = h * b2[1];
        sc[2] = Wf[0]; sc[3] = Wf[1]; sc[4] = Wf[2]; sc[5] = Wf[3];
        sc[6] = bf[0]; sc[7] = bf[1];

        int tv = tptr[0];
        if (tv <= 0 || tv > 100000) tv = (int)__int_as_float(tv);
        double tf = 0.1 * (double)tv;
        double tt = 0.0;
        int n = 0;
        while (tt <= tf) { n++; tt += 0.01; }
        s_nsteps = n;
    }
    __syncthreads();

    const int i = blockIdx.x * TPB + tid;     // pair index: points 2i, 2i+1
    const int npairs = B >> 1;
    if (i >= npairs) return;

    float4 xv = reinterpret_cast<const float4*>(x)[i];
    u64 y0p = pk2(xv.x, xv.z);
    u64 y1p = pk2(xv.y, xv.w);

    const int nsteps = s_nsteps;
    const u64 hb20p = pk2(sc[0], sc[0]);
    const u64 hb21p = pk2(sc[1], sc[1]);
    const u64 halfp = pk2(0.5f, 0.5f);
    const u64 twop  = pk2(2.0f, 2.0f);
    const u64 sixth = pk2(1.0f / 6.0f, 1.0f / 6.0f);

    for (int s = 0; s < nsteps; s++) {
        u64 k10, k11, k20, k21, k30, k31, k40, k41;
        geval2(y0p, y1p, sA, sB, sC, hb20p, hb21p, k10, k11);
        geval2(fma2(halfp, k10, y0p), fma2(halfp, k11, y1p),
               sA, sB, sC, hb20p, hb21p, k20, k21);
        geval2(fma2(halfp, k20, y0p), fma2(halfp, k21, y1p),
               sA, sB, sC, hb20p, hb21p, k30, k31);
        geval2(add2(y0p, k30), add2(y1p, k31),
               sA, sB, sC, hb20p, hb21p, k40, k41);

        u64 s0 = fma2(twop, add2(k20, k30), add2(k10, k40));
        u64 s1 = fma2(twop, add2(k21, k31), add2(k11, k41));
        y0p = fma2(sixth, s0, y0p);
        y1p = fma2(sixth, s1, y1p);
    }

    float y0a, y0b, y1a, y1b;
    upk2(y0p, y0a, y0b);
    upk2(y1p, y1a, y1b);

    const float wf00 = sc[2], wf01 = sc[3], wf10 = sc[4], wf11 = sc[5];
    const float bf0 = sc[6], bf1 = sc[7];

    float l0a = __fmaf_rn(y0a, wf00, __fmaf_rn(y1a, wf10, bf0));
    float l1a = __fmaf_rn(y0a, wf01, __fmaf_rn(y1a, wf11, bf1));
    float l0b = __fmaf_rn(y0b, wf00, __fmaf_rn(y1b, wf10, bf0));
    float l1b = __fmaf_rn(y0b, wf01, __fmaf_rn(y1b, wf11, bf1));

    float ma = fmaxf(l0a, l1a), mb = fmaxf(l0b, l1b);
    float e0a = __expf(l0a - ma), e1a = __expf(l1a - ma);
    float e0b = __expf(l0b - mb), e1b = __expf(l1b - mb);
    float ia = 1.0f / (e0a + e1a), ib = 1.0f / (e0b + e1b);

    float4* outL = reinterpret_cast<float4*>(out);
    float4* outP = reinterpret_cast<float4*>(out + 2 * B);
    outL[i] = make_float4(l0a, l1a, l0b, l1b);
    outP[i] = make_float4(e0a * ia, e1a * ia, e0b * ib, e1b * ib);
}

extern "C" void kernel_launch(void* const* d_in, const int* in_sizes, int n_in,
                              void* d_out, int out_size)
{
    const float* x  = (const float*)d_in[0];
    const float* W1 = (const float*)d_in[1];
    const float* b1 = (const float*)d_in[2];
    const float* W2 = (const float*)d_in[3];
    const float* b2 = (const float*)d_in[4];
    const float* Wf = (const float*)d_in[5];
    const float* bf = (const float*)d_in[6];
    const int*   t  = (const int*)d_in[7];
    float* out = (float*)d_out;

    const int B = in_sizes[0] / 2;
    const int npairs = B / 2;
    const int grid = (npairs + TPB - 1) / TPB;
    node_rk4_kernel<<<grid, TPB>>>(x, W1, b1, W2, b2, Wf, bf, t, out, B);
}

// round 4
// speedup vs baseline: 1.1109x; 1.1109x over previous
#include <cuda_runtime.h>
#include <cuda_bf16.h>
#include <cstdint>

#define HID 256
#define TPB 32

typedef unsigned long long u64;
typedef unsigned int u32;

__device__ __forceinline__ u64 pk2(float a, float b) {
    u64 r; asm("mov.b64 %0, {%1, %2};" : "=l"(r) : "f"(a), "f"(b)); return r;
}
__device__ __forceinline__ void upk2(u64 v, float& lo, float& hi) {
    asm("mov.b64 {%0, %1}, %2;" : "=f"(lo), "=f"(hi) : "l"(v));
}
__device__ __forceinline__ u64 fma2(u64 a, u64 b, u64 c) {
    u64 d; asm("fma.rn.f32x2 %0, %1, %2, %3;" : "=l"(d) : "l"(a), "l"(b), "l"(c)); return d;
}
__device__ __forceinline__ u64 add2(u64 a, u64 b) {
    u64 d; asm("add.rn.f32x2 %0, %1, %2;" : "=l"(d) : "l"(a), "l"(b)); return d;
}
__device__ __forceinline__ u64 tanh2(u64 v) {
    float lo, hi, tl, th;
    upk2(v, lo, hi);
    asm("tanh.approx.f32 %0, %1;" : "=f"(tl) : "f"(lo));
    asm("tanh.approx.f32 %0, %1;" : "=f"(th) : "f"(hi));
    return pk2(tl, th);
}
__device__ __forceinline__ void lds2(u32 addr, u64& a, u64& b) {
    asm volatile("ld.shared.v2.u64 {%0, %1}, [%2];" : "=l"(a), "=l"(b) : "r"(addr));
}

// SMEM: per 2j-block, 10 u64 (80B):
//  [Ax0,Ay0, Bx0,By0, C0,Ax1, Ay1,Bx1, By1,C1]
//  Ax={W1[0][j]}x2  Ay={W1[1][j]}x2  Bx={b1[j]}x2  By={h*W2[j][0]}x2  C={h*W2[j][1]}x2
__shared__ u64 s_w[(HID / 2) * 10];

__device__ __forceinline__ void geval4(u64 y0A, u64 y1A, u64 y0B, u64 y1B,
                                       u32 wbase,
                                       u64 hb20p, u64 hb21p,
                                       u64& o0A, u64& o1A, u64& o0B, u64& o1B)
{
    u64 a0A = 0ull, a1A = 0ull, a0B = 0ull, a1B = 0ull;
    u32 addr = wbase;
#pragma unroll 4
    for (int blk = 0; blk < HID / 2; blk++, addr += 80) {
        u64 w0, w1, w2, w3, w4, w5, w6, w7, w8, w9;
        lds2(addr,      w0, w1);
        lds2(addr + 16, w2, w3);
        lds2(addr + 32, w4, w5);
        lds2(addr + 48, w6, w7);
        lds2(addr + 64, w8, w9);

        // unit 0: Ax=w0 Ay=w1 Bx=w2 By=w3 C=w4
        {
            u64 pA = fma2(w0, y0A, fma2(w1, y1A, w2));
            u64 pB = fma2(w0, y0B, fma2(w1, y1B, w2));
            u64 tA = tanh2(pA);
            u64 tB = tanh2(pB);
            a0A = fma2(tA, w3, a0A);  a1A = fma2(tA, w4, a1A);
            a0B = fma2(tB, w3, a0B);  a1B = fma2(tB, w4, a1B);
        }
        // unit 1: Ax=w5 Ay=w6 Bx=w7 By=w8 C=w9
        {
            u64 pA = fma2(w5, y0A, fma2(w6, y1A, w7));
            u64 pB = fma2(w5, y0B, fma2(w6, y1B, w7));
            u64 tA = tanh2(pA);
            u64 tB = tanh2(pB);
            a0A = fma2(tA, w8, a0A);  a1A = fma2(tA, w9, a1A);
            a0B = fma2(tB, w8, a0B);  a1B = fma2(tB, w9, a1B);
        }
    }
    o0A = add2(a0A, hb20p);  o1A = add2(a1A, hb21p);
    o0B = add2(a0B, hb20p);  o1B = add2(a1B, hb21p);
}

__global__ __launch_bounds__(TPB)
void node_rk4_kernel(const float* __restrict__ x,
                     const float* __restrict__ W1,
                     const float* __restrict__ b1,
                     const float* __restrict__ W2,
                     const float* __restrict__ b2,
                     const float* __restrict__ Wf,
                     const float* __restrict__ bf,
                     const int*   __restrict__ tptr,
                     float* __restrict__ out,
                     int B)
{
    __shared__ float sc[8];
    __shared__ int   s_nsteps;

    const float h = 0.01f;
    const int tid = threadIdx.x;

    for (int j = tid; j < HID; j += TPB) {
        float wx = W1[j], wy = W1[HID + j], bb = b1[j];
        float wa = h * W2[2 * j], wb = h * W2[2 * j + 1];
        int base = (j >> 1) * 10 + (j & 1) * 5;
        s_w[base + 0] = pk2(wx, wx);
        s_w[base + 1] = pk2(wy, wy);
        s_w[base + 2] = pk2(bb, bb);
        s_w[base + 3] = pk2(wa, wa);
        s_w[base + 4] = pk2(wb, wb);
    }
    if (tid == 0) {
        sc[0] = h * b2[0]; sc[1] = h * b2[1];
        sc[2] = Wf[0]; sc[3] = Wf[1]; sc[4] = Wf[2]; sc[5] = Wf[3];
        sc[6] = bf[0]; sc[7] = bf[1];

        int tv = tptr[0];
        if (tv <= 0 || tv > 100000) tv = (int)__int_as_float(tv);
        double tf = 0.1 * (double)tv;
        double tt = 0.0;
        int n = 0;
        while (tt <= tf) { n++; tt += 0.01; }
        s_nsteps = n;
    }
    __syncthreads();

    u32 wbase = (u32)__cvta_generic_to_shared(s_w);

    const int q = blockIdx.x * TPB + tid;     // quad index: points 4q..4q+3
    const int nquads = B >> 2;
    if (q >= nquads) return;

    float4 xv0 = reinterpret_cast<const float4*>(x)[2 * q + 0];
    float4 xv1 = reinterpret_cast<const float4*>(x)[2 * q + 1];
    u64 y0A = pk2(xv0.x, xv0.z), y1A = pk2(xv0.y, xv0.w);
    u64 y0B = pk2(xv1.x, xv1.z), y1B = pk2(xv1.y, xv1.w);

    const int nsteps = s_nsteps;
    const u64 hb20p = pk2(sc[0], sc[0]);
    const u64 hb21p = pk2(sc[1], sc[1]);
    const u64 halfp = pk2(0.5f, 0.5f);
    const u64 twop  = pk2(2.0f, 2.0f);
    const u64 sixth = pk2(1.0f / 6.0f, 1.0f / 6.0f);

    for (int s = 0; s < nsteps; s++) {
        u64 k0A, k1A, k0B, k1B;
        u64 ac0A, ac1A, ac0B, ac1B;

        // k1
        geval4(y0A, y1A, y0B, y1B, wbase, hb20p, hb21p, k0A, k1A, k0B, k1B);
        ac0A = k0A; ac1A = k1A; ac0B = k0B; ac1B = k1B;

        // k2
        geval4(fma2(halfp, k0A, y0A), fma2(halfp, k1A, y1A),
               fma2(halfp, k0B, y0B), fma2(halfp, k1B, y1B),
               wbase, hb20p, hb21p, k0A, k1A, k0B, k1B);
        ac0A = fma2(twop, k0A, ac0A); ac1A = fma2(twop, k1A, ac1A);
        ac0B = fma2(twop, k0B, ac0B); ac1B = fma2(twop, k1B, ac1B);

        // k3
        geval4(fma2(halfp, k0A, y0A), fma2(halfp, k1A, y1A),
               fma2(halfp, k0B, y0B), fma2(halfp, k1B, y1B),
               wbase, hb20p, hb21p, k0A, k1A, k0B, k1B);
        ac0A = fma2(twop, k0A, ac0A); ac1A = fma2(twop, k1A, ac1A);
        ac0B = fma2(twop, k0B, ac0B); ac1B = fma2(twop, k1B, ac1B);

        // k4
        geval4(add2(y0A, k0A), add2(y1A, k1A),
               add2(y0B, k0B), add2(y1B, k1B),
               wbase, hb20p, hb21p, k0A, k1A, k0B, k1B);
        ac0A = add2(ac0A, k0A); ac1A = add2(ac1A, k1A);
        ac0B = add2(ac0B, k0B); ac1B = add2(ac1B, k1B);

        y0A = fma2(sixth, ac0A, y0A); y1A = fma2(sixth, ac1A, y1A);
        y0B = fma2(sixth, ac0B, y0B); y1B = fma2(sixth, ac1B, y1B);
    }

    const float wf00 = sc[2], wf01 = sc[3], wf10 = sc[4], wf11 = sc[5];
    const float bf0 = sc[6], bf1 = sc[7];

    float y0a, y0b, y1a, y1b, y0c, y0d, y1c, y1d;
    upk2(y0A, y0a, y0b);  upk2(y1A, y1a, y1b);
    upk2(y0B, y0c, y0d);  upk2(y1B, y1c, y1d);

    float4* outL = reinterpret_cast<float4*>(out);
    float4* outP = reinterpret_cast<float4*>(out + 2 * B);

    {
        float l0a = __fmaf_rn(y0a, wf00, __fmaf_rn(y1a, wf10, bf0));
        float l1a = __fmaf_rn(y0a, wf01, __fmaf_rn(y1a, wf11, bf1));
        float l0b = __fmaf_rn(y0b, wf00, __fmaf_rn(y1b, wf10, bf0));
        float l1b = __fmaf_rn(y0b, wf01, __fmaf_rn(y1b, wf11, bf1));
        float ma = fmaxf(l0a, l1a), mb = fmaxf(l0b, l1b);
        float e0a = __expf(l0a - ma), e1a = __expf(l1a - ma);
        float e0b = __expf(l0b - mb), e1b = __expf(l1b - mb);
        float ia = 1.0f / (e0a + e1a), ib = 1.0f / (e0b + e1b);
        outL[2 * q + 0] = make_float4(l0a, l1a, l0b, l1b);
        outP[2 * q + 0] = make_float4(e0a * ia, e1a * ia, e0b * ib, e1b * ib);
    }
    {
        float l0a = __fmaf_rn(y0c, wf00, __fmaf_rn(y1c, wf10, bf0));
        float l1a = __fmaf_rn(y0c, wf01, __fmaf_rn(y1c, wf11, bf1));
        float l0b = __fmaf_rn(y0d, wf00, __fmaf_rn(y1d, wf10, bf0));
        float l1b = __fmaf_rn(y0d, wf01, __fmaf_rn(y1d, wf11, bf1));
        float ma = fmaxf(l0a, l1a), mb = fmaxf(l0b, l1b);
        float e0a = __expf(l0a - ma), e1a = __expf(l1a - ma);
        float e0b = __expf(l0b - mb), e1b = __expf(l1b - mb);
        float ia = 1.0f / (e0a + e1a), ib = 1.0f / (e0b + e1b);
        outL[2 * q + 1] = make_float4(l0a, l1a, l0b, l1b);
        outP[2 * q + 1] = make_float4(e0a * ia, e1a * ia, e0b * ib, e1b * ib);
    }
}

extern "C" void kernel_launch(void* const* d_in, const int* in_sizes, int n_in,
                              void* d_out, int out_size)
{
    const float* x  = (const float*)d_in[0];
    const float* W1 = (const float*)d_in[1];
    const float* b1 = (const float*)d_in[2];
    const float* W2 = (const float*)d_in[3];
    const float* b2 = (const float*)d_in[4];
    const float* Wf = (const float*)d_in[5];
    const float* bf = (const float*)d_in[6];
    const int*   t  = (const int*)d_in[7];
    float* out = (float*)d_out;

    const int B = in_sizes[0] / 2;
    const int nquads = B / 4;
    const int grid = (nquads + TPB - 1) / TPB;
    node_rk4_kernel<<<grid, TPB>>>(x, W1, b1, W2, b2, Wf, bf, t, out, B);
}